// round 15
// baseline (speedup 1.0000x reference)
#include <cuda_runtime.h>
#include <math.h>

#define NN   8192
#define CHN  128
#define BBS  16
#define NSEQ 512
#define NHD  8
#define DH   16
#define NE   131072

__device__ __forceinline__ unsigned cvt_tf32(float f) {
    unsigned u; asm("cvt.rna.tf32.f32 %0,%1;" : "=r"(u) : "f"(f)); return u;
}
__device__ __forceinline__ void mma_tf32(float* c, const unsigned* a, const unsigned* b) {
    asm volatile("mma.sync.aligned.m16n8k8.row.col.f32.tf32.tf32.f32 "
                 "{%0,%1,%2,%3},{%4,%5,%6,%7},{%8,%9},{%0,%1,%2,%3};"
                 : "+f"(c[0]), "+f"(c[1]), "+f"(c[2]), "+f"(c[3])
                 : "r"(a[0]), "r"(a[1]), "r"(a[2]), "r"(a[3]), "r"(b[0]), "r"(b[1]));
}

// ---------------- scratch ----------------
__device__ float g_qkvc[NN*512];          // [xw | q*scale | k | v]
__device__ float g_att [NN*CHN];
__device__ float g_t1  [NN*CHN];
__device__ float g_t2  [NN*CHN];
__device__ float g_ot  [NN*CHN];
__device__ float g_mlp1[NN*2*CHN];
__device__ float g_t3  [NN*CHN];
__device__ float g_Wp  [CHN*512];
__device__ float g_Bp  [512];
__device__ int   g_cnt [NN];
__device__ int   g_off [NN+1];
__device__ int   g_cur [NN];
__device__ int   g_ssrc[NE];
__device__ float g_dinv[NN];
__device__ float g_psum [128*CHN];
__device__ float g_psq  [128*CHN];
__device__ float g_psum2[128*CHN];
__device__ float g_psq2 [128*CHN];
__device__ float g_mean[3][CHN];
__device__ float g_rstd[3][CHN];

// ---------------- CSR build ----------------
__global__ void k_zero() {
    int i = blockIdx.x*blockDim.x + threadIdx.x;
    if (i < NN) { g_cnt[i] = 0; g_cur[i] = 0; }
}
__global__ void k_hist(const int* __restrict__ ei) {
    int e = blockIdx.x*blockDim.x + threadIdx.x;
    if (e < NE) atomicAdd(&g_cnt[ei[NE + e]], 1);
}
__global__ void k_scan() {
    __shared__ int sm[1024];
    int t = threadIdx.x;
    int base = t*8;
    int v[8];
#pragma unroll
    for (int j = 0; j < 8; j++) v[j] = g_cnt[base+j];
    int tot = 0;
#pragma unroll
    for (int j = 0; j < 8; j++) { int tmp = v[j]; v[j] = tot; tot += tmp; }
    sm[t] = tot;
    __syncthreads();
    for (int off = 1; off < 1024; off <<= 1) {
        int val = sm[t];
        int add = (t >= off) ? sm[t-off] : 0;
        __syncthreads();
        sm[t] = val + add;
        __syncthreads();
    }
    int excl = (t == 0) ? 0 : sm[t-1];
#pragma unroll
    for (int j = 0; j < 8; j++) g_off[base+j] = excl + v[j];
    if (t == 1023) g_off[NN] = sm[1023];
#pragma unroll
    for (int j = 0; j < 8; j++)
        g_dinv[base+j] = rsqrtf(1.0f + (float)g_cnt[base+j]);
}
__global__ void k_fill(const int* __restrict__ ei) {
    int e = blockIdx.x*blockDim.x + threadIdx.x;
    if (e < NE) {
        int src = ei[e];
        int dst = ei[NE + e];
        int pos = atomicAdd(&g_cur[dst], 1);
        g_ssrc[g_off[dst] + pos] = src;
    }
}

// ---------------- weight pack ----------------
__global__ void k_pack(const float* __restrict__ cw,
                       const float* __restrict__ wq, const float* __restrict__ bq,
                       const float* __restrict__ wk, const float* __restrict__ bk,
                       const float* __restrict__ wv, const float* __restrict__ bv) {
    int i = blockIdx.x*blockDim.x + threadIdx.x;
    int r = i >> 9, c = i & 511;
    float v;
    if      (c < 128) v = cw[r*128 + c];
    else if (c < 256) v = wq[r*128 + (c-128)] * 0.25f;
    else if (c < 384) v = wk[r*128 + (c-256)];
    else              v = wv[r*128 + (c-384)];
    g_Wp[i] = v;
    if (r == 0) {
        float b = 0.f;
        if      (c >= 384) b = bv[c-384];
        else if (c >= 256) b = bk[c-256];
        else if (c >= 128) b = bq[c-128]*0.25f;
        g_Bp[c] = b;
    }
}

// ---------------- GCN gather ----------------
__global__ void k_gather(const float* __restrict__ x, const float* __restrict__ conv_b) {
    int dst = blockIdx.x;
    int ch  = threadIdx.x;
    float di  = g_dinv[dst];
    float acc = g_qkvc[(size_t)dst*512 + ch] * di;
    int s0 = g_off[dst], s1 = g_off[dst+1];
    for (int i = s0; i < s1; i++) {
        int s = g_ssrc[i];
        acc += g_qkvc[(size_t)s*512 + ch] * g_dinv[s];
    }
    g_t1[dst*CHN + ch] = acc*di + conv_b[ch] + x[dst*CHN + ch];
}

// ---------------- tf32 tensor-core GEMM: 128x64 block, reg double-buffered ----------------
template<int K, int N, bool RELU>
__global__ __launch_bounds__(256) void k_gemm(const float* __restrict__ A,
                                              const float* __restrict__ W,
                                              const float* __restrict__ bias,
                                              const float* __restrict__ resid,
                                              float* __restrict__ out) {
    __shared__ float As[16][136];
    __shared__ float Bs[16][72];
    const int bm = blockIdx.y;
    const int bn = blockIdx.x;
    const int tid = threadIdx.x;
    const int w = tid >> 5, lane = tid & 31;
    const int g = lane >> 2, tig = lane & 3;
    const int wm = w >> 1, wn = w & 1;

    const int ar = tid >> 1;
    const int ac = (tid & 1) * 8;
    const int br = tid >> 4;
    const int bc = (tid & 15) * 4;

    float c[2][4][4];
#pragma unroll
    for (int mi = 0; mi < 2; mi++)
#pragma unroll
        for (int ni = 0; ni < 4; ni++)
#pragma unroll
            for (int j = 0; j < 4; j++) c[mi][ni][j] = 0.f;

    const float* Ap = A + (size_t)(bm*128 + ar)*K + ac;
    const float* Wp = W + (size_t)br*N + bn*64 + bc;

    float4 a0 = *(const float4*)(Ap);
    float4 a1 = *(const float4*)(Ap + 4);
    float4 bv = *(const float4*)(Wp);

    for (int k0 = 0; k0 < K; k0 += 16) {
        As[ac+0][ar]=a0.x; As[ac+1][ar]=a0.y; As[ac+2][ar]=a0.z; As[ac+3][ar]=a0.w;
        As[ac+4][ar]=a1.x; As[ac+5][ar]=a1.y; As[ac+6][ar]=a1.z; As[ac+7][ar]=a1.w;
        *(float4*)&Bs[br][bc] = bv;
        __syncthreads();
        if (k0 + 16 < K) {
            a0 = *(const float4*)(Ap + k0 + 16);
            a1 = *(const float4*)(Ap + k0 + 20);
            bv = *(const float4*)(Wp + (size_t)(k0+16)*N);
        }
#pragma unroll
        for (int ks = 0; ks < 16; ks += 8) {
            unsigned af[2][4];
#pragma unroll
            for (int mi = 0; mi < 2; mi++) {
                int mb = wm*32 + mi*16;
                af[mi][0] = cvt_tf32(As[ks+tig  ][mb+g  ]);
                af[mi][1] = cvt_tf32(As[ks+tig  ][mb+g+8]);
                af[mi][2] = cvt_tf32(As[ks+tig+4][mb+g  ]);
                af[mi][3] = cvt_tf32(As[ks+tig+4][mb+g+8]);
            }
            unsigned bf[4][2];
#pragma unroll
            for (int ni = 0; ni < 4; ni++) {
                int nb = wn*32 + ni*8;
                bf[ni][0] = cvt_tf32(Bs[ks+tig  ][nb+g]);
                bf[ni][1] = cvt_tf32(Bs[ks+tig+4][nb+g]);
            }
#pragma unroll
            for (int mi = 0; mi < 2; mi++)
#pragma unroll
                for (int ni = 0; ni < 4; ni++)
                    mma_tf32(c[mi][ni], af[mi], bf[ni]);
        }
        __syncthreads();
    }

#pragma unroll
    for (int mi = 0; mi < 2; mi++) {
        int row0 = bm*128 + wm*32 + mi*16 + g;
#pragma unroll
        for (int ni = 0; ni < 4; ni++) {
            int col = bn*64 + wn*32 + ni*8 + tig*2;
            float bx = 0.f, by = 0.f;
            if (bias) { bx = bias[col]; by = bias[col+1]; }
            float v0 = c[mi][ni][0] + bx;
            float v1 = c[mi][ni][1] + by;
            float v2 = c[mi][ni][2] + bx;
            float v3 = c[mi][ni][3] + by;
            if (RELU) {
                v0 = fmaxf(v0, 0.f); v1 = fmaxf(v1, 0.f);
                v2 = fmaxf(v2, 0.f); v3 = fmaxf(v3, 0.f);
            }
            if (resid) {
                float2 r0 = *(const float2*)&resid[(size_t)row0*N + col];
                float2 r1 = *(const float2*)&resid[(size_t)(row0+8)*N + col];
                v0 += r0.x; v1 += r0.y; v2 += r1.x; v3 += r1.y;
            }
            *(float2*)&out[(size_t)row0*N + col]     = make_float2(v0, v1);
            *(float2*)&out[(size_t)(row0+8)*N + col] = make_float2(v2, v3);
        }
    }
}

// ---------------- tensor-core flash attention: 32-q tile, double-buffered staging ----------------
#define BSTR 132
#define KSTR 20
// one staging buffer: K (2560) + V (2560) + B (4224) = 9344 floats
#define SBUF   (NHD*16*KSTR*2 + 32*BSTR)
#define OFF_P2 (2*SBUF)                        // 18688
#define SMEM_FLOATS (OFF_P2 + NHD*32*KSTR)     // 23808 floats (95,232 B)

__global__ __launch_bounds__(256, 2) void k_attn(const float* __restrict__ bias) {
    extern __shared__ float sm[];
    float* Psm = sm + OFF_P2;

    const int b  = blockIdx.y;
    const int q0 = blockIdx.x * 32;
    const int tid = threadIdx.x;
    const int h   = tid >> 5;
    const int lane = tid & 31;
    const int g   = lane >> 2;
    const int tig = lane & 3;

    unsigned aq[2][2][4];
#pragma unroll
    for (int mi = 0; mi < 2; mi++)
#pragma unroll
        for (int kk = 0; kk < 2; kk++) {
            const float* qb = g_qkvc + ((size_t)(b*NSEQ + q0 + mi*16 + g))*512 + 128 + h*DH + kk*8;
            aq[mi][kk][0] = cvt_tf32(qb[tig]);
            aq[mi][kk][1] = cvt_tf32(qb[8*512 + tig]);
            aq[mi][kk][2] = cvt_tf32(qb[tig + 4]);
            aq[mi][kk][3] = cvt_tf32(qb[8*512 + tig + 4]);
        }

    const int lq  = tid >> 3;
    const int lqu = tid & 7;
    const size_t bbase = ((size_t)(b*NSEQ + q0 + lq))*4096 + lqu*16;
    const int lkr = tid >> 4;
    const int lhh = tid & 15;
    const int kh2 = lhh >> 1;
    const int kd0 = (lhh & 1) * 8;

    float4 pb[4];
    float4 pk[2], pv[2];
#pragma unroll
    for (int j = 0; j < 4; j++) pb[j] = *(const float4*)(bias + bbase + j*4);
    {
        const float* kp = g_qkvc + ((size_t)(b*NSEQ + lkr))*512 + 256 + lhh*8;
        const float* vp = g_qkvc + ((size_t)(b*NSEQ + lkr))*512 + 384 + lhh*8;
        pk[0] = *(const float4*)kp;  pk[1] = *(const float4*)(kp+4);
        pv[0] = *(const float4*)vp;  pv[1] = *(const float4*)(vp+4);
    }
    // stage chunk 0 into buffer 0
    {
        float* Kc = sm;  float* Vc = sm + NHD*16*KSTR;  float* Bc = sm + NHD*16*KSTR*2;
#pragma unroll
        for (int j = 0; j < 4; j++)
            *(float4*)&Bc[lq*BSTR + lqu*16 + j*4] = pb[j];
        *(float4*)&Kc[kh2*(16*KSTR) + lkr*KSTR + kd0]     = pk[0];
        *(float4*)&Kc[kh2*(16*KSTR) + lkr*KSTR + kd0 + 4] = pk[1];
        *(float4*)&Vc[kh2*(16*KSTR) + lkr*KSTR + kd0]     = pv[0];
        *(float4*)&Vc[kh2*(16*KSTR) + lkr*KSTR + kd0 + 4] = pv[1];
    }
    __syncthreads();

    float srow[4];
#pragma unroll
    for (int r = 0; r < 4; r++) srow[r] = 0.f;
    float cO[2][2][4];
#pragma unroll
    for (int mi = 0; mi < 2; mi++)
#pragma unroll
        for (int n0 = 0; n0 < 2; n0++)
#pragma unroll
            for (int j = 0; j < 4; j++) cO[mi][n0][j] = 0.f;

    for (int i = 0; i < 32; i++) {
        float* Kc = sm + (i & 1)*SBUF;
        float* Vc = Kc + NHD*16*KSTR;
        float* Bc = Kc + NHD*16*KSTR*2;

        // issue global loads for chunk i+1 (consumed by store after compute)
        if (i < 31) {
#pragma unroll
            for (int j = 0; j < 4; j++) pb[j] = *(const float4*)(bias + bbase + (size_t)(i+1)*128 + j*4);
            const float* kp = g_qkvc + ((size_t)(b*NSEQ + (i+1)*16 + lkr))*512 + 256 + lhh*8;
            const float* vp = g_qkvc + ((size_t)(b*NSEQ + (i+1)*16 + lkr))*512 + 384 + lhh*8;
            pk[0] = *(const float4*)kp;  pk[1] = *(const float4*)(kp+4);
            pv[0] = *(const float4*)vp;  pv[1] = *(const float4*)(vp+4);
        }

        // ---- S = bias + Q K^T ----
        float cS[2][2][4];
#pragma unroll
        for (int mi = 0; mi < 2; mi++)
#pragma unroll
            for (int n0 = 0; n0 < 2; n0++) {
                int base = (mi*16 + g)*BSTR + (n0*8 + tig*2)*8 + h;
                cS[mi][n0][0] = Bc[base];
                cS[mi][n0][1] = Bc[base + 8];
                cS[mi][n0][2] = Bc[base + 8*BSTR];
                cS[mi][n0][3] = Bc[base + 8*BSTR + 8];
            }
        unsigned bk[2][2][2];
#pragma unroll
        for (int kk = 0; kk < 2; kk++)
#pragma unroll
            for (int n0 = 0; n0 < 2; n0++) {
                bk[kk][n0][0] = cvt_tf32(Kc[h*(16*KSTR) + (n0*8 + g)*KSTR + kk*8 + tig]);
                bk[kk][n0][1] = cvt_tf32(Kc[h*(16*KSTR) + (n0*8 + g)*KSTR + kk*8 + tig + 4]);
            }
#pragma unroll
        for (int mi = 0; mi < 2; mi++)
#pragma unroll
            for (int n0 = 0; n0 < 2; n0++) {
                mma_tf32(cS[mi][n0], aq[mi][0], bk[0][n0]);
                mma_tf32(cS[mi][n0], aq[mi][1], bk[1][n0]);
            }

        // ---- exp (no max) + partial row sums ----
#pragma unroll
        for (int mi = 0; mi < 2; mi++)
#pragma unroll
            for (int n0 = 0; n0 < 2; n0++) {
                float e0 = __expf(cS[mi][n0][0]);
                float e1 = __expf(cS[mi][n0][1]);
                float e2 = __expf(cS[mi][n0][2]);
                float e3 = __expf(cS[mi][n0][3]);
                cS[mi][n0][0] = e0; cS[mi][n0][1] = e1;
                cS[mi][n0][2] = e2; cS[mi][n0][3] = e3;
                srow[mi*2]   += e0 + e1;
                srow[mi*2+1] += e2 + e3;
            }

        // ---- P transpose through per-warp smem ----
        float* Pw = Psm + h*(32*KSTR);
#pragma unroll
        for (int mi = 0; mi < 2; mi++)
#pragma unroll
            for (int n0 = 0; n0 < 2; n0++) {
                int base = (mi*16 + g)*KSTR + n0*8 + tig*2;
                Pw[base]            = cS[mi][n0][0];
                Pw[base + 1]        = cS[mi][n0][1];
                Pw[base + 8*KSTR]   = cS[mi][n0][2];
                Pw[base + 8*KSTR+1] = cS[mi][n0][3];
            }
        __syncwarp();

        unsigned ap[2][2][4];
#pragma unroll
        for (int mi = 0; mi < 2; mi++)
#pragma unroll
            for (int kk = 0; kk < 2; kk++) {
                int base = (mi*16 + g)*KSTR + kk*8;
                ap[mi][kk][0] = cvt_tf32(Pw[base + tig]);
                ap[mi][kk][1] = cvt_tf32(Pw[base + 8*KSTR + tig]);
                ap[mi][kk][2] = cvt_tf32(Pw[base + tig + 4]);
                ap[mi][kk][3] = cvt_tf32(Pw[base + 8*KSTR + tig + 4]);
            }

        unsigned bv2[2][2][2];
#pragma unroll
        for (int kk = 0; kk < 2; kk++)
#pragma unroll
            for (int n0 = 0; n0 < 2; n0++) {
                bv2[kk][n0][0] = cvt_tf32(Vc[h*(16*KSTR) + (kk*8 + tig)*KSTR + n0*8 + g]);
                bv2[kk][n0][1] = cvt_tf32(Vc[h*(16*KSTR) + (kk*8 + tig + 4)*KSTR + n0*8 + g]);
            }
#pragma unroll
        for (int mi = 0; mi < 2; mi++)
#pragma unroll
            for (int n0 = 0; n0 < 2; n0++) {
                mma_tf32(cO[mi][n0], ap[mi][0], bv2[0][n0]);
                mma_tf32(cO[mi][n0], ap[mi][1], bv2[1][n0]);
            }

        // ---- stage chunk i+1 into the other buffer (readers passed last sync) ----
        if (i < 31) {
            float* Kn = sm + ((i+1) & 1)*SBUF;
            float* Vn = Kn + NHD*16*KSTR;
            float* Bn = Kn + NHD*16*KSTR*2;
#pragma unroll
            for (int j = 0; j < 4; j++)
                *(float4*)&Bn[lq*BSTR + lqu*16 + j*4] = pb[j];
            *(float4*)&Kn[kh2*(16*KSTR) + lkr*KSTR + kd0]     = pk[0];
            *(float4*)&Kn[kh2*(16*KSTR) + lkr*KSTR + kd0 + 4] = pk[1];
            *(float4*)&Vn[kh2*(16*KSTR) + lkr*KSTR + kd0]     = pv[0];
            *(float4*)&Vn[kh2*(16*KSTR) + lkr*KSTR + kd0 + 4] = pv[1];
        }
        __syncthreads();
    }

    // ---- epilogue: reduce row sums, normalize, write ----
#pragma unroll
    for (int mi = 0; mi < 2; mi++) {
        float se = srow[mi*2];
        float so = srow[mi*2+1];
        se += __shfl_xor_sync(0xffffffffu, se, 1);
        se += __shfl_xor_sync(0xffffffffu, se, 2);
        so += __shfl_xor_sync(0xffffffffu, so, 1);
        so += __shfl_xor_sync(0xffffffffu, so, 2);
        float ive = 1.0f / se;
        float ivo = 1.0f / so;
        int rowe = b*NSEQ + q0 + mi*16 + g;
#pragma unroll
        for (int n0 = 0; n0 < 2; n0++) {
            int col = h*DH + n0*8 + tig*2;
            *(float2*)&g_att[(size_t)rowe*CHN + col] =
                make_float2(cO[mi][n0][0]*ive, cO[mi][n0][1]*ive);
            *(float2*)&g_att[(size_t)(rowe+8)*CHN + col] =
                make_float2(cO[mi][n0][2]*ivo, cO[mi][n0][3]*ivo);
        }
    }
}

// ---------------- BatchNorm ----------------
__global__ void k_statsA(const float* __restrict__ in) {
    int ch = threadIdx.x;
    int cb = blockIdx.x;
    float s = 0.f, q = 0.f;
    for (int r = cb*64; r < cb*64 + 64; r++) {
        float v = in[(size_t)r*CHN + ch];
        s += v; q = fmaf(v, v, q);
    }
    g_psum[cb*CHN + ch] = s;
    g_psq [cb*CHN + ch] = q;
}
__global__ void k_statsB(const float* __restrict__ in) {
    int ch = threadIdx.x;
    int cb = blockIdx.x;
    float s = 0.f, q = 0.f;
    for (int r = cb*64; r < cb*64 + 64; r++) {
        float v = in[(size_t)r*CHN + ch];
        s += v; q = fmaf(v, v, q);
    }
    g_psum2[cb*CHN + ch] = s;
    g_psq2 [cb*CHN + ch] = q;
}
__global__ void k_stats_fin2() {
    int ch = threadIdx.x;
    float s1=0.f,q1=0.f,s2=0.f,q2=0.f;
    for (int i = 0; i < 128; i++) {
        s1 += g_psum [i*CHN + ch]; q1 += g_psq [i*CHN + ch];
        s2 += g_psum2[i*CHN + ch]; q2 += g_psq2[i*CHN + ch];
    }
    float m1 = s1*(1.0f/NN), m2 = s2*(1.0f/NN);
    g_mean[0][ch] = m1; g_rstd[0][ch] = rsqrtf(q1*(1.0f/NN) - m1*m1 + 1e-5f);
    g_mean[1][ch] = m2; g_rstd[1][ch] = rsqrtf(q2*(1.0f/NN) - m2*m2 + 1e-5f);
}
__global__ void k_stats_fin(int idx) {
    int ch = threadIdx.x;
    float s = 0.f, q = 0.f;
    for (int i = 0; i < 128; i++) { s += g_psum[i*CHN + ch]; q += g_psq[i*CHN + ch]; }
    float mean = s * (1.0f/NN);
    float var  = q * (1.0f/NN) - mean*mean;
    g_mean[idx][ch] = mean;
    g_rstd[idx][ch] = rsqrtf(var + 1e-5f);
}
__global__ void k_combine(const float* __restrict__ g1, const float* __restrict__ be1,
                          const float* __restrict__ g2, const float* __restrict__ be2) {
    int i = blockIdx.x*blockDim.x + threadIdx.x;
    int ch = i & (CHN-1);
    float a = (g_t1[i] - g_mean[0][ch]) * g_rstd[0][ch] * g1[ch] + be1[ch];
    float b = (g_t2[i] - g_mean[1][ch]) * g_rstd[1][ch] * g2[ch] + be2[ch];
    g_ot[i] = a + b;
}
__global__ void k_final(const float* __restrict__ g3, const float* __restrict__ be3,
                        float* __restrict__ out) {
    int i = blockIdx.x*blockDim.x + threadIdx.x;
    int ch = i & (CHN-1);
    out[i] = (g_t3[i] - g_mean[2][ch]) * g_rstd[2][ch] * g3[ch] + be3[ch];
}

// ---------------- launch (fork/join graph) ----------------
extern "C" void kernel_launch(void* const* d_in, const int* in_sizes, int n_in,
                              void* d_out, int out_size) {
    const float* x      = (const float*)d_in[0];
    const int*   ei     = (const int*)  d_in[1];
    const float* abias  = (const float*)d_in[3];
    const float* conv_w = (const float*)d_in[4];
    const float* conv_b = (const float*)d_in[5];
    const float* wq = (const float*)d_in[6];  const float* bq = (const float*)d_in[7];
    const float* wk = (const float*)d_in[8];  const float* bk = (const float*)d_in[9];
    const float* wv = (const float*)d_in[10]; const float* bv = (const float*)d_in[11];
    const float* wo = (const float*)d_in[12]; const float* bo = (const float*)d_in[13];
    const float* w1 = (const float*)d_in[14]; const float* b1 = (const float*)d_in[15];
    const float* w2 = (const float*)d_in[16]; const float* b2 = (const float*)d_in[17];
    const float* g1 = (const float*)d_in[18]; const float* be1 = (const float*)d_in[19];
    const float* g2 = (const float*)d_in[20]; const float* be2 = (const float*)d_in[21];
    const float* g3 = (const float*)d_in[22]; const float* be3 = (const float*)d_in[23];
    float* out = (float*)d_out;

    float *p_qkvc, *p_att, *p_t1, *p_t2, *p_ot, *p_mlp1, *p_t3, *p_Wp, *p_Bp;
    cudaGetSymbolAddress((void**)&p_qkvc, g_qkvc);
    cudaGetSymbolAddress((void**)&p_att,  g_att);
    cudaGetSymbolAddress((void**)&p_t1,   g_t1);
    cudaGetSymbolAddress((void**)&p_t2,   g_t2);
    cudaGetSymbolAddress((void**)&p_ot,   g_ot);
    cudaGetSymbolAddress((void**)&p_mlp1, g_mlp1);
    cudaGetSymbolAddress((void**)&p_t3,   g_t3);
    cudaGetSymbolAddress((void**)&p_Wp,   g_Wp);
    cudaGetSymbolAddress((void**)&p_Bp,   g_Bp);

    const int ATTN_SMEM = SMEM_FLOATS * (int)sizeof(float);   // 95,232 B
    cudaFuncSetAttribute(k_attn, cudaFuncAttributeMaxDynamicSharedMemorySize, ATTN_SMEM);

    cudaStream_t s2;
    cudaStreamCreateWithFlags(&s2, cudaStreamNonBlocking);
    cudaEvent_t eFork, eJoin;
    cudaEventCreateWithFlags(&eFork, cudaEventDisableTiming);
    cudaEventCreateWithFlags(&eJoin, cudaEventDisableTiming);

    // prologue on main stream (launches #1, #2)
    k_pack<<<CHN*512/256, 256>>>(conv_w, wq, bq, wk, bk, wv, bv);
    k_gemm<128,512,false><<<dim3(8,64), 256>>>(x, p_Wp, p_Bp, nullptr, p_qkvc);

    // fork: first part of side branch (#3,#4,#5) so attn is launch #6 for ncu
    cudaEventRecord(eFork, 0);
    cudaStreamWaitEvent(s2, eFork, 0);
    k_zero<<<32, 256, 0, s2>>>();
    k_hist<<<NE/256, 256, 0, s2>>>(ei);
    k_scan<<<1, 1024, 0, s2>>>();

    // main branch: attention (#6) -> Wo -> BN2 stats
    k_attn<<<dim3(NSEQ/32, BBS), 256, ATTN_SMEM>>>(abias);

    // rest of side branch
    k_fill<<<NE/256, 256, 0, s2>>>(ei);
    k_gather<<<NN, 128, 0, s2>>>(x, conv_b);
    k_statsA<<<128, 128, 0, s2>>>(p_t1);
    cudaEventRecord(eJoin, s2);

    k_gemm<128,128,false><<<dim3(2,64), 256>>>(p_att, wo, bo, x, p_t2);
    k_statsB<<<128, 128>>>(p_t2);

    // join, finalize BN1+BN2, combine
    cudaStreamWaitEvent(0, eJoin, 0);
    k_stats_fin2<<<1,128>>>();
    k_combine<<<NN*CHN/256, 256>>>(g1, be1, g2, be2);

    // MLP with residual
    k_gemm<128,256,true ><<<dim3(4,64), 256>>>(p_ot,   w1, b1, nullptr, p_mlp1);
    k_gemm<256,128,false><<<dim3(2,64), 256>>>(p_mlp1, w2, b2, p_ot,    p_t3);

    // BN3 -> output
    k_statsA<<<128,128>>>(p_t3);
    k_stats_fin<<<1,128>>>(2);
    k_final<<<NN*CHN/256, 256>>>(g3, be3, out);
}